// round 14
// baseline (speedup 1.0000x reference)
#include <cuda_runtime.h>
#include <cuda_fp16.h>
#include <math.h>
#include <stdint.h>

#define NN 50000
#define EE 800000
#define FIN 256
#define HID 128
#define NCLS 40

#define SCB 512
#define NSB ((NN + SCB - 1) / SCB)  // 98

// ---------------- scratch (device globals; no allocation allowed) ----------------
__device__ int   g_is64;
__device__ int   g_dst[EE];
__device__ int   g_deg[NN];
__device__ float g_dinv[NN];
__device__ int   g_off[NN + 1];
__device__ int   g_cursor[NN];
__device__ int   g_bsum[NSB];
__device__ __align__(16) int2  g_csrw[EE];  // (src, dinv[src] bits)

// fp16 operands
__device__ __align__(16) __half g_xh[(size_t)NN * FIN];
__device__ __align__(16) __half g_w1t[384 * 256];   // [N=384][K=256]
__device__ __align__(16) __half g_w2t[120 * 384];   // [N=120][K=384]
__device__ __align__(16) __half g_hh[(size_t)NN * 384];

// fp16 gather buffers for the SpMM chain
__device__ __align__(16) __half g_Gh[(size_t)NN * 256];  // x@[W1|W2]
__device__ __align__(16) __half g_Uh[(size_t)NN * 128];  // U[:,128:256]
__device__ __align__(16) __half g_Fh[(size_t)NN * 80];   // F[:,40:120]
__device__ __align__(16) __half g_Rh[(size_t)NN * 40];   // R[:,40:80]

__device__ __align__(16) float g_Fp[(size_t)NN * 120];   // split-K partial F (fp32)
__device__ __align__(16) float g_Fb[(size_t)NN * 120];   // only cols 0:40 written/read
__device__ __align__(16) float g_Rb[(size_t)NN * 80];    // only cols 0:40 written/read

// ---------------- helpers ----------------
__device__ __forceinline__ uint32_t smem_u32(const void* p) {
    uint32_t a;
    asm("{ .reg .u64 t; cvta.to.shared.u64 t, %1; cvt.u32.u64 %0, t; }" : "=r"(a) : "l"(p));
    return a;
}

__device__ __forceinline__ void ldm_x4(uint32_t* r, uint32_t addr) {
    asm volatile("ldmatrix.sync.aligned.m8n8.x4.shared.b16 {%0,%1,%2,%3}, [%4];"
                 : "=r"(r[0]), "=r"(r[1]), "=r"(r[2]), "=r"(r[3]) : "r"(addr));
}

__device__ __forceinline__ void mma_f16(float* d, const uint32_t* a, uint32_t b0, uint32_t b1) {
    asm volatile(
        "mma.sync.aligned.m16n8k16.row.col.f32.f16.f16.f32 "
        "{%0,%1,%2,%3}, {%4,%5,%6,%7}, {%8,%9}, {%0,%1,%2,%3};"
        : "+f"(d[0]), "+f"(d[1]), "+f"(d[2]), "+f"(d[3])
        : "r"(a[0]), "r"(a[1]), "r"(a[2]), "r"(a[3]), "r"(b0), "r"(b1));
}

// ---------------- preprocessing ----------------
__global__ void k_zerodetect(const int2* __restrict__ ei2, int n, int e) {
    int i = blockIdx.x * blockDim.x + threadIdx.x;
    if (i < n) g_deg[i] = 0;
    if (blockIdx.x == 0) {
        __shared__ int nonzero;
        if (threadIdx.x == 0) nonzero = 0;
        __syncthreads();
        int t = threadIdx.x;
        if (t < 256 && t < e) {
            int2 p = ei2[t];
            if (p.y != 0) atomicAdd(&nonzero, 1);
        }
        __syncthreads();
        if (threadIdx.x == 0) g_is64 = (nonzero == 0) ? 1 : 0;
    }
}

__global__ void k_convdeg(const void* __restrict__ ei, int e) {
    int t = blockIdx.x * blockDim.x + threadIdx.x;
    if (t >= e) return;
    int d;
    if (g_is64) d = (int)((const long long*)ei)[(size_t)e + t];
    else        d = ((const int*)ei)[e + t];
    g_dst[t] = d;
    atomicAdd(&g_deg[d], 1);
}

// -------- hierarchical scan (dinv fused into phase 1) --------
__global__ __launch_bounds__(SCB) void k_scan1(int n) {
    __shared__ int wsum[SCB / 32];
    int tid = threadIdx.x, lane = tid & 31, wid = tid >> 5;
    int i = blockIdx.x * SCB + tid;
    int v = 0;
    if (i < n) {
        v = g_deg[i];
        g_dinv[i] = rsqrtf((float)(v + 1));  // +1 self loop
    }
    int inc = v;
    #pragma unroll
    for (int o = 1; o < 32; o <<= 1) {
        int t = __shfl_up_sync(0xffffffffu, inc, o);
        if (lane >= o) inc += t;
    }
    if (lane == 31) wsum[wid] = inc;
    __syncthreads();
    if (wid == 0) {
        int w = (lane < SCB / 32) ? wsum[lane] : 0;
        #pragma unroll
        for (int o = 1; o < SCB / 32; o <<= 1) {
            int t = __shfl_up_sync(0xffffffffu, w, o);
            if (lane >= o) w += t;
        }
        if (lane < SCB / 32) wsum[lane] = w;
    }
    __syncthreads();
    int ex = (inc - v) + (wid ? wsum[wid - 1] : 0);
    if (i < n) g_off[i] = ex;
    if (tid == SCB - 1) g_bsum[blockIdx.x] = ex + v;
}

__global__ void k_scan2() {
    int lane = threadIdx.x;
    int carry = 0;
    for (int b = 0; b < NSB; b += 32) {
        int idx = b + lane;
        int v = (idx < NSB) ? g_bsum[idx] : 0;
        int inc = v;
        #pragma unroll
        for (int o = 1; o < 32; o <<= 1) {
            int t = __shfl_up_sync(0xffffffffu, inc, o);
            if (lane >= o) inc += t;
        }
        int ex = carry + inc - v;
        if (idx < NSB) g_bsum[idx] = ex;
        carry += __shfl_sync(0xffffffffu, inc, 31);
    }
}

__global__ void k_scan3(int n, int e_total) {
    int i = blockIdx.x * blockDim.x + threadIdx.x;
    if (i < n) {
        int o = g_off[i] + g_bsum[i / SCB];
        g_off[i] = o;
        g_cursor[i] = o;
    }
    if (i == 0) g_off[n] = e_total;
}

__global__ void k_scatter(const void* __restrict__ ei, int e) {
    int t = blockIdx.x * blockDim.x + threadIdx.x;
    if (t >= e) return;
    int s;
    if (g_is64) s = (int)((const long long*)ei)[t];
    else        s = ((const int*)ei)[t];
    int d = g_dst[t];
    int p = atomicAdd(&g_cursor[d], 1);
    g_csrw[p] = make_int2(s, __float_as_int(g_dinv[s]));
}

// ---------------- data conversion ----------------
__global__ void k_xhalf(const float* __restrict__ x, int total4) {
    int i = blockIdx.x * blockDim.x + threadIdx.x;
    if (i >= total4) return;
    float4 v = ((const float4*)x)[i];
    ((__half2*)g_xh)[i * 2] = __floats2half2_rn(v.x, v.y);
    ((__half2*)g_xh)[i * 2 + 1] = __floats2half2_rn(v.z, v.w);
}

__global__ void k_wsplit(const float* __restrict__ w10, const float* __restrict__ w11,
                         const float* __restrict__ w12, const float* __restrict__ w20,
                         const float* __restrict__ w21, const float* __restrict__ w22) {
    int g = blockIdx.x * blockDim.x + threadIdx.x;
    if (g < 384 * 256) {
        int n = g / 256, k = g % 256;
        const float* w = (n < 128) ? w10 : (n < 256) ? w11 : w12;
        g_w1t[g] = __float2half_rn(w[k * 128 + (n & 127)]);
    } else if (g < 384 * 256 + 120 * 384) {
        int g2 = g - 384 * 256;
        int n = g2 / 384, k = g2 % 384;
        const float* w = (n < 40) ? w20 : (n < 80) ? w21 : w22;
        g_w2t[g2] = __float2half_rn(w[k * 40 + (n % 40)]);
    }
}

// ---------------- mma1 (layer 1, fp16, sync loads) ----------------
#define SPITCH 72
#define OFF_A 0
#define OFF_B (128 * SPITCH)
#define SMEMSZ (2 * 128 * SPITCH * 2)  // 36864 bytes

__device__ __forceinline__ void ld_tile_sm(__half* dst, const __half* __restrict__ src,
                                           int row0, int validRows, int pitch, int k0, int tid) {
    #pragma unroll
    for (int it = 0; it < 4; it++) {
        int slot = tid + it * 256;
        int row = slot >> 3, q = slot & 7;
        float4 v = make_float4(0.f, 0.f, 0.f, 0.f);
        if (row < validRows)
            v = *reinterpret_cast<const float4*>(src + (size_t)(row0 + row) * pitch + k0 + q * 8);
        *reinterpret_cast<float4*>(dst + row * SPITCH + q * 8) = v;
    }
}

__global__ __launch_bounds__(256) void k_mma1(const float* __restrict__ b1, int M) {
    extern __shared__ __align__(16) __half sm[];
    uint32_t sbase = smem_u32(sm);

    int tid = threadIdx.x;
    int warp = tid >> 5, lane = tid & 31;
    int wm = warp & 3, wn = warp >> 2;
    int rowSel = lane & 15;
    int kSel = (lane >> 4) << 3;

    int bm = blockIdx.y * 128, bn = blockIdx.x * 128;
    int rowsA = M - bm; if (rowsA > 128) rowsA = 128;

    float acc[2][8][4];
    #pragma unroll
    for (int i = 0; i < 2; i++)
        #pragma unroll
        for (int j = 0; j < 8; j++)
            #pragma unroll
            for (int q = 0; q < 4; q++) acc[i][j][q] = 0.f;

    for (int c = 0; c < 4; c++) {
        int k0 = c * 64;
        ld_tile_sm(sm + OFF_A, g_xh, bm, rowsA, 256, k0, tid);
        ld_tile_sm(sm + OFF_B, g_w1t, bn, 128, 256, k0, tid);
        __syncthreads();
        #pragma unroll
        for (int kb = 0; kb < 64; kb += 16) {
            uint32_t aH[2][4];
            #pragma unroll
            for (int i = 0; i < 2; i++) {
                uint32_t rowA = wm * 32 + i * 16 + rowSel;
                ldm_x4(aH[i], sbase + 2u * (OFF_A + rowA * SPITCH + kb + kSel));
            }
            #pragma unroll
            for (int jj = 0; jj < 4; jj++) {
                uint32_t bH[4];
                uint32_t rowB = wn * 64 + jj * 16 + rowSel;
                ldm_x4(bH, sbase + 2u * (OFF_B + rowB * SPITCH + kb + kSel));
                #pragma unroll
                for (int i = 0; i < 2; i++) {
                    mma_f16(acc[i][2 * jj], aH[i], bH[0], bH[2]);
                    mma_f16(acc[i][2 * jj + 1], aH[i], bH[1], bH[3]);
                }
            }
        }
        __syncthreads();
    }

    int g = lane >> 2, tg = lane & 3;
    int m0 = bm + wm * 32;
    int nb = wn * 64;
    #pragma unroll
    for (int i = 0; i < 2; i++) {
        int r0 = m0 + i * 16 + g;
        int r1 = r0 + 8;
        #pragma unroll
        for (int j = 0; j < 8; j++) {
            int cl = nb + j * 8 + tg * 2;
            float2 v0 = make_float2(acc[i][j][0], acc[i][j][1]);
            float2 v1 = make_float2(acc[i][j][2], acc[i][j][3]);
            if (blockIdx.x == 0) {
                float2 bb = *(const float2*)&b1[cl];
                if (r0 < M)
                    *(__half2*)&g_hh[(size_t)r0 * 384 + cl] = __floats2half2_rn(
                        fmaxf(v0.x + bb.x, 0.f), fmaxf(v0.y + bb.y, 0.f));
                if (r1 < M)
                    *(__half2*)&g_hh[(size_t)r1 * 384 + cl] = __floats2half2_rn(
                        fmaxf(v1.x + bb.x, 0.f), fmaxf(v1.y + bb.y, 0.f));
            } else {
                int cg = (blockIdx.x - 1) * 128 + cl;
                if (r0 < M)
                    *(__half2*)&g_Gh[(size_t)r0 * 256 + cg] = __floats2half2_rn(v0.x, v0.y);
                if (r1 < M)
                    *(__half2*)&g_Gh[(size_t)r1 * 256 + cg] = __floats2half2_rn(v1.x, v1.y);
            }
        }
    }
}

// ---------------- mma2 split-K part (layer 2): K chunk PART*128 .. PART*128+128 ----------------
// PART 0: Fp = acc ; PART 1: Fp += acc ; PART 2: final = Fp + acc -> Fb (0:40 fp32) + Fh (40:120 fp16)
template <int PART>
__global__ __launch_bounds__(256) void k_mma2p(int M) {
    extern __shared__ __align__(16) __half sm[];
    uint32_t sbase = smem_u32(sm);

    int tid = threadIdx.x;
    int warp = tid >> 5, lane = tid & 31;
    int wm = warp & 3, wn = warp >> 2;
    int rowSel = lane & 15;
    int kSel = (lane >> 4) << 3;

    int bm = blockIdx.y * 128;
    int rowsA = M - bm; if (rowsA > 128) rowsA = 128;

    const __half* Ah = g_hh + PART * 128;      // row pitch 384
    const __half* Bh = g_w2t + PART * 128;     // row pitch 384, 120 rows

    float acc[2][8][4];
    #pragma unroll
    for (int i = 0; i < 2; i++)
        #pragma unroll
        for (int j = 0; j < 8; j++)
            #pragma unroll
            for (int q = 0; q < 4; q++) acc[i][j][q] = 0.f;

    for (int c = 0; c < 2; c++) {
        int k0 = c * 64;
        ld_tile_sm(sm + OFF_A, Ah, bm, rowsA, 384, k0, tid);
        ld_tile_sm(sm + OFF_B, Bh, 0, 120, 384, k0, tid);
        __syncthreads();
        #pragma unroll
        for (int kb = 0; kb < 64; kb += 16) {
            uint32_t aH[2][4];
            #pragma unroll
            for (int i = 0; i < 2; i++) {
                uint32_t rowA = wm * 32 + i * 16 + rowSel;
                ldm_x4(aH[i], sbase + 2u * (OFF_A + rowA * SPITCH + kb + kSel));
            }
            #pragma unroll
            for (int jj = 0; jj < 4; jj++) {
                uint32_t bH[4];
                uint32_t rowB = wn * 64 + jj * 16 + rowSel;
                ldm_x4(bH, sbase + 2u * (OFF_B + rowB * SPITCH + kb + kSel));
                #pragma unroll
                for (int i = 0; i < 2; i++) {
                    mma_f16(acc[i][2 * jj], aH[i], bH[0], bH[2]);
                    mma_f16(acc[i][2 * jj + 1], aH[i], bH[1], bH[3]);
                }
            }
        }
        __syncthreads();
    }

    int g = lane >> 2, tg = lane & 3;
    int m0 = bm + wm * 32;
    int nb = wn * 64;
    #pragma unroll
    for (int i = 0; i < 2; i++) {
        int r0 = m0 + i * 16 + g;
        int r1 = r0 + 8;
        #pragma unroll
        for (int j = 0; j < 8; j++) {
            int cl = nb + j * 8 + tg * 2;
            if (cl >= 120) continue;
            float2 v0 = make_float2(acc[i][j][0], acc[i][j][1]);
            float2 v1 = make_float2(acc[i][j][2], acc[i][j][3]);
            if (PART == 0) {
                if (r0 < M) *(float2*)&g_Fp[(size_t)r0 * 120 + cl] = v0;
                if (r1 < M) *(float2*)&g_Fp[(size_t)r1 * 120 + cl] = v1;
            } else if (PART == 1) {
                if (r0 < M) {
                    float2 p = *(const float2*)&g_Fp[(size_t)r0 * 120 + cl];
                    *(float2*)&g_Fp[(size_t)r0 * 120 + cl] = make_float2(p.x + v0.x, p.y + v0.y);
                }
                if (r1 < M) {
                    float2 p = *(const float2*)&g_Fp[(size_t)r1 * 120 + cl];
                    *(float2*)&g_Fp[(size_t)r1 * 120 + cl] = make_float2(p.x + v1.x, p.y + v1.y);
                }
            } else {
                if (r0 < M) {
                    float2 p = *(const float2*)&g_Fp[(size_t)r0 * 120 + cl];
                    float2 f = make_float2(p.x + v0.x, p.y + v0.y);
                    if (cl < 40) *(float2*)&g_Fb[(size_t)r0 * 120 + cl] = f;
                    else *(__half2*)&g_Fh[(size_t)r0 * 80 + (cl - 40)] = __floats2half2_rn(f.x, f.y);
                }
                if (r1 < M) {
                    float2 p = *(const float2*)&g_Fp[(size_t)r1 * 120 + cl];
                    float2 f = make_float2(p.x + v1.x, p.y + v1.y);
                    if (cl < 40) *(float2*)&g_Fb[(size_t)r1 * 120 + cl] = f;
                    else *(__half2*)&g_Fh[(size_t)r1 * 80 + (cl - 40)] = __floats2half2_rn(f.x, f.y);
                }
            }
        }
    }
}

// ---------------- SpMM (fp16 gather, fp32 accumulate, 2-edge unroll) ----------------
// WHICH 0: g_Gh(256) -> h[:,128:256] (fp16 relu+b1) + g_Uh(128)
// WHICH 1: g_Uh(128) -> h[:,256:384] (fp16 relu+b1)
// WHICH 2: g_Fh(80)  -> g_Rb[:,0:40] fp32 + g_Rh(40)
// WHICH 3: g_Rh(40)  -> fused bias + log_softmax -> out
template <int NH, int WHICH>
__global__ __launch_bounds__(256) void k_spmmh(const float* __restrict__ b1,
                                               const float* __restrict__ b2,
                                               float* __restrict__ out, int n) {
    constexpr int IT = (NH + 127) / 128;
    const __half* __restrict__ in =
        (WHICH == 0) ? g_Gh : (WHICH == 1) ? g_Uh : (WHICH == 2) ? g_Fh : g_Rh;

    int w = (blockIdx.x * blockDim.x + threadIdx.x) >> 5;
    int lane = threadIdx.x & 31;
    if (w >= n) return;
    float di = g_dinv[w];

    float4 acc[IT];
    #pragma unroll
    for (int t = 0; t < IT; t++) {
        int c = t * 128 + lane * 4;
        acc[t] = make_float4(0, 0, 0, 0);
        if (c < NH) {
            uint2 u = *(const uint2*)(in + (size_t)w * NH + c);
            float2 f0 = __half22float2(*(__half2*)&u.x);
            float2 f1 = __half22float2(*(__half2*)&u.y);
            acc[t] = make_float4(di * f0.x, di * f0.y, di * f1.x, di * f1.y);
        }
    }
    int jb = g_off[w], je = g_off[w + 1];
    int j = jb;
    for (; j + 1 < je; j += 2) {
        int2 e0 = __ldg(&g_csrw[j]);
        int2 e1 = __ldg(&g_csrw[j + 1]);
        float w0 = __int_as_float(e0.y);
        float w1 = __int_as_float(e1.y);
        uint2 u0[IT], u1[IT];
        #pragma unroll
        for (int t = 0; t < IT; t++) {
            int c = t * 128 + lane * 4;
            if (c < NH) {
                u0[t] = __ldg((const uint2*)(in + (size_t)e0.x * NH + c));
                u1[t] = __ldg((const uint2*)(in + (size_t)e1.x * NH + c));
            }
        }
        #pragma unroll
        for (int t = 0; t < IT; t++) {
            int c = t * 128 + lane * 4;
            if (c < NH) {
                float2 a0 = __half22float2(*(__half2*)&u0[t].x);
                float2 a1 = __half22float2(*(__half2*)&u0[t].y);
                float2 b0 = __half22float2(*(__half2*)&u1[t].x);
                float2 b1h = __half22float2(*(__half2*)&u1[t].y);
                acc[t].x += w0 * a0.x + w1 * b0.x;
                acc[t].y += w0 * a0.y + w1 * b0.y;
                acc[t].z += w0 * a1.x + w1 * b1h.x;
                acc[t].w += w0 * a1.y + w1 * b1h.y;
            }
        }
    }
    if (j < je) {
        int2 e0 = __ldg(&g_csrw[j]);
        float w0 = __int_as_float(e0.y);
        #pragma unroll
        for (int t = 0; t < IT; t++) {
            int c = t * 128 + lane * 4;
            if (c < NH) {
                uint2 u = __ldg((const uint2*)(in + (size_t)e0.x * NH + c));
                float2 f0 = __half22float2(*(__half2*)&u.x);
                float2 f1 = __half22float2(*(__half2*)&u.y);
                acc[t].x += w0 * f0.x;
                acc[t].y += w0 * f0.y;
                acc[t].z += w0 * f1.x;
                acc[t].w += w0 * f1.y;
            }
        }
    }

    if (WHICH == 3) {
        float4 sv = make_float4(di * acc[0].x, di * acc[0].y, di * acc[0].z, di * acc[0].w);
        float4 v = make_float4(0, 0, 0, 0);
        if (lane < 10)
            v = *(const float4*)&g_Fb[(size_t)w * 120 + lane * 4];
        else if (lane < 20)
            v = *(const float4*)&g_Rb[(size_t)w * 80 + (lane - 10) * 4];
        int srcl = (lane >= 20) ? (lane - 20) : 0;
        float sx = __shfl_sync(0xffffffffu, sv.x, srcl);
        float sy = __shfl_sync(0xffffffffu, sv.y, srcl);
        float sz = __shfl_sync(0xffffffffu, sv.z, srcl);
        float sw = __shfl_sync(0xffffffffu, sv.w, srcl);
        if (lane >= 20 && lane < 30) v = make_float4(sx, sy, sz, sw);
        bool act = lane < 30;
        if (act) {
            float4 bb = ((const float4*)b2)[lane];
            v.x += bb.x; v.y += bb.y; v.z += bb.z; v.w += bb.w;
        }
        float m = act ? fmaxf(fmaxf(v.x, v.y), fmaxf(v.z, v.w)) : -INFINITY;
        #pragma unroll
        for (int o = 16; o > 0; o >>= 1) m = fmaxf(m, __shfl_xor_sync(0xffffffffu, m, o));
        float s = 0.0f;
        if (act) s = expf(v.x - m) + expf(v.y - m) + expf(v.z - m) + expf(v.w - m);
        #pragma unroll
        for (int o = 16; o > 0; o >>= 1) s += __shfl_xor_sync(0xffffffffu, s, o);
        float lse = m + logf(s);
        if (act) {
            float4 r = make_float4(v.x - lse, v.y - lse, v.z - lse, v.w - lse);
            ((float4*)out)[(size_t)w * 30 + lane] = r;
        }
        return;
    }

    #pragma unroll
    for (int t = 0; t < IT; t++) {
        int c = t * 128 + lane * 4;
        if (c >= NH) continue;
        float4 ov = make_float4(di * acc[t].x, di * acc[t].y, di * acc[t].z, di * acc[t].w);
        if (WHICH == 0) {
            if (c < 128) {
                int col = 128 + c;
                float4 bb = *(const float4*)&b1[col];
                __half2 q0 = __floats2half2_rn(fmaxf(ov.x + bb.x, 0.f), fmaxf(ov.y + bb.y, 0.f));
                __half2 q1 = __floats2half2_rn(fmaxf(ov.z + bb.z, 0.f), fmaxf(ov.w + bb.w, 0.f));
                *(__half2*)&g_hh[(size_t)w * 384 + col] = q0;
                *(__half2*)&g_hh[(size_t)w * 384 + col + 2] = q1;
            } else {
                __half2 q0 = __floats2half2_rn(ov.x, ov.y);
                __half2 q1 = __floats2half2_rn(ov.z, ov.w);
                uint2 u;
                u.x = *(uint32_t*)&q0;
                u.y = *(uint32_t*)&q1;
                *(uint2*)&g_Uh[(size_t)w * 128 + (c - 128)] = u;
            }
        } else if (WHICH == 1) {
            int col = 256 + c;
            float4 bb = *(const float4*)&b1[col];
            __half2 q0 = __floats2half2_rn(fmaxf(ov.x + bb.x, 0.f), fmaxf(ov.y + bb.y, 0.f));
            __half2 q1 = __floats2half2_rn(fmaxf(ov.z + bb.z, 0.f), fmaxf(ov.w + bb.w, 0.f));
            *(__half2*)&g_hh[(size_t)w * 384 + col] = q0;
            *(__half2*)&g_hh[(size_t)w * 384 + col + 2] = q1;
        } else {  // WHICH == 2
            if (c < 40) {
                *(float4*)&g_Rb[(size_t)w * 80 + c] = ov;
            } else {
                __half2 q0 = __floats2half2_rn(ov.x, ov.y);
                __half2 q1 = __floats2half2_rn(ov.z, ov.w);
                uint2 u;
                u.x = *(uint32_t*)&q0;
                u.y = *(uint32_t*)&q1;
                *(uint2*)&g_Rh[(size_t)w * 40 + (c - 40)] = u;
            }
        }
    }
}

// ---------------- launch ----------------
extern "C" void kernel_launch(void* const* d_in, const int* in_sizes, int n_in,
                              void* d_out, int out_size) {
    const float* x = (const float*)d_in[0];
    const void* ei = d_in[1];
    const float* W1_0 = (const float*)d_in[2];
    const float* W1_1 = (const float*)d_in[3];
    const float* W1_2 = (const float*)d_in[4];
    const float* b1 = (const float*)d_in[5];
    const float* W2_0 = (const float*)d_in[6];
    const float* W2_1 = (const float*)d_in[7];
    const float* W2_2 = (const float*)d_in[8];
    const float* b2 = (const float*)d_in[9];
    float* out = (float*)d_out;

    int n = in_sizes[0] / FIN;  // 50000
    int e = in_sizes[1] / 2;    // 800000

    static cudaStream_t s2 = nullptr;
    static cudaEvent_t evFork = nullptr, evW = nullptr, evJoin = nullptr;
    static cudaEvent_t evM1 = nullptr, evS0 = nullptr, evB = nullptr;
    if (s2 == nullptr) {
        cudaStreamCreateWithFlags(&s2, cudaStreamNonBlocking);
        cudaEventCreateWithFlags(&evFork, cudaEventDisableTiming);
        cudaEventCreateWithFlags(&evW, cudaEventDisableTiming);
        cudaEventCreateWithFlags(&evJoin, cudaEventDisableTiming);
        cudaEventCreateWithFlags(&evM1, cudaEventDisableTiming);
        cudaEventCreateWithFlags(&evS0, cudaEventDisableTiming);
        cudaEventCreateWithFlags(&evB, cudaEventDisableTiming);
        cudaFuncSetAttribute(k_mma1, cudaFuncAttributeMaxDynamicSharedMemorySize, SMEMSZ);
        cudaFuncSetAttribute(k_mma2p<0>, cudaFuncAttributeMaxDynamicSharedMemorySize, SMEMSZ);
        cudaFuncSetAttribute(k_mma2p<1>, cudaFuncAttributeMaxDynamicSharedMemorySize, SMEMSZ);
        cudaFuncSetAttribute(k_mma2p<2>, cudaFuncAttributeMaxDynamicSharedMemorySize, SMEMSZ);
    }

    int mt = (n + 127) / 128;
    int sb = (n + 7) / 8;

    // ---- fork: weight conversion + graph preprocessing on s2 ----
    cudaEventRecord(evFork, 0);
    cudaStreamWaitEvent(s2, evFork, 0);

    k_wsplit<<<(384 * 256 + 120 * 384 + 255) / 256, 256, 0, s2>>>(W1_0, W1_1, W1_2,
                                                                  W2_0, W2_1, W2_2);
    cudaEventRecord(evW, s2);
    k_zerodetect<<<(n + 255) / 256, 256, 0, s2>>>((const int2*)ei, n, e);
    k_convdeg<<<(e + 255) / 256, 256, 0, s2>>>(ei, e);
    k_scan1<<<NSB, SCB, 0, s2>>>(n);
    k_scan2<<<1, 32, 0, s2>>>();
    k_scan3<<<(n + 255) / 256, 256, 0, s2>>>(n, e);
    k_scatter<<<(e + 255) / 256, 256, 0, s2>>>(ei, e);
    cudaEventRecord(evJoin, s2);

    // ---- main: x conversion + layer-1 GEMM ----
    k_xhalf<<<(n * FIN / 4 + 255) / 256, 256>>>(x, n * FIN / 4);
    cudaStreamWaitEvent(0, evW, 0);
    k_mma1<<<dim3(3, mt), 256, SMEMSZ>>>(b1, n);   // [h0 | Gh]
    cudaEventRecord(evM1, 0);

    // s2: mma2 part a (K 0:128, needs h0) runs parallel to spmm0
    cudaStreamWaitEvent(s2, evM1, 0);
    k_mma2p<0><<<dim3(1, mt), 256, SMEMSZ, s2>>>(n);

    // main: spmm chain
    cudaStreamWaitEvent(0, evJoin, 0);
    k_spmmh<256, 0><<<sb, 256>>>(b1, b2, out, n);  // h[:,128:256] + Uh
    cudaEventRecord(evS0, 0);

    // s2: mma2 part b (K 128:256, needs h1) runs parallel to spmm1
    cudaStreamWaitEvent(s2, evS0, 0);
    k_mma2p<1><<<dim3(1, mt), 256, SMEMSZ, s2>>>(n);
    cudaEventRecord(evB, s2);

    k_spmmh<128, 1><<<sb, 256>>>(b1, b2, out, n);  // h[:,256:384]

    cudaStreamWaitEvent(0, evB, 0);
    k_mma2p<2><<<dim3(1, mt), 256, SMEMSZ>>>(n);   // final F -> Fb/Fh

    k_spmmh<80, 2><<<sb, 256>>>(b1, b2, out, n);   // R
    k_spmmh<40, 3><<<sb, 256>>>(b1, b2, out, n);   // S + fused log_softmax
}

// round 15
// speedup vs baseline: 1.1534x; 1.1534x over previous
#include <cuda_runtime.h>
#include <cuda_fp16.h>
#include <math.h>
#include <stdint.h>

#define NN 50000
#define EE 800000
#define FIN 256
#define HID 128
#define NCLS 40

#define SCB 512
#define NSB ((NN + SCB - 1) / SCB)  // 98

// ---------------- scratch (device globals; no allocation allowed) ----------------
__device__ int   g_is64;
__device__ int   g_dst[EE];
__device__ int   g_deg[NN];
__device__ float g_dinv[NN];
__device__ int   g_off[NN + 1];
__device__ int   g_cursor[NN];
__device__ int   g_bsum[NSB];
__device__ __align__(16) int2  g_csrw[EE];  // (src, dinv[src] bits)

// fp16 operands
__device__ __align__(16) __half g_xh[(size_t)NN * FIN];
__device__ __align__(16) __half g_w1t[384 * 256];   // [N=384][K=256]
__device__ __align__(16) __half g_w2t[120 * 384];   // [N=120][K=384]
__device__ __align__(16) __half g_hh[(size_t)NN * 384];

// fp16 gather buffers for the SpMM chain
__device__ __align__(16) __half g_Gh[(size_t)NN * 256];  // x@[W1|W2]
__device__ __align__(16) __half g_Uh[(size_t)NN * 128];  // U[:,128:256]
__device__ __align__(16) __half g_Fh[(size_t)NN * 80];   // F[:,40:120]
__device__ __align__(16) __half g_Rh[(size_t)NN * 40];   // R[:,40:80]

__device__ __align__(16) float g_Fb[(size_t)NN * 120];   // fp32 for final softmax
__device__ __align__(16) float g_Rb[(size_t)NN * 80];

// ---------------- helpers ----------------
__device__ __forceinline__ uint32_t smem_u32(const void* p) {
    uint32_t a;
    asm("{ .reg .u64 t; cvta.to.shared.u64 t, %1; cvt.u32.u64 %0, t; }" : "=r"(a) : "l"(p));
    return a;
}

__device__ __forceinline__ void ldm_x4(uint32_t* r, uint32_t addr) {
    asm volatile("ldmatrix.sync.aligned.m8n8.x4.shared.b16 {%0,%1,%2,%3}, [%4];"
                 : "=r"(r[0]), "=r"(r[1]), "=r"(r[2]), "=r"(r[3]) : "r"(addr));
}

__device__ __forceinline__ void mma_f16(float* d, const uint32_t* a, uint32_t b0, uint32_t b1) {
    asm volatile(
        "mma.sync.aligned.m16n8k16.row.col.f32.f16.f16.f32 "
        "{%0,%1,%2,%3}, {%4,%5,%6,%7}, {%8,%9}, {%0,%1,%2,%3};"
        : "+f"(d[0]), "+f"(d[1]), "+f"(d[2]), "+f"(d[3])
        : "r"(a[0]), "r"(a[1]), "r"(a[2]), "r"(a[3]), "r"(b0), "r"(b1));
}

// ---------------- preprocessing ----------------
__global__ void k_zerodetect(const int2* __restrict__ ei2, int n, int e) {
    int i = blockIdx.x * blockDim.x + threadIdx.x;
    if (i < n) g_deg[i] = 0;
    if (blockIdx.x == 0) {
        __shared__ int nonzero;
        if (threadIdx.x == 0) nonzero = 0;
        __syncthreads();
        int t = threadIdx.x;
        if (t < 256 && t < e) {
            int2 p = ei2[t];
            if (p.y != 0) atomicAdd(&nonzero, 1);
        }
        __syncthreads();
        if (threadIdx.x == 0) g_is64 = (nonzero == 0) ? 1 : 0;
    }
}

__global__ void k_convdeg(const void* __restrict__ ei, int e) {
    int t = blockIdx.x * blockDim.x + threadIdx.x;
    if (t >= e) return;
    int d;
    if (g_is64) d = (int)((const long long*)ei)[(size_t)e + t];
    else        d = ((const int*)ei)[e + t];
    g_dst[t] = d;
    atomicAdd(&g_deg[d], 1);
}

__global__ void k_dinv(int n) {
    int i = blockIdx.x * blockDim.x + threadIdx.x;
    if (i < n) g_dinv[i] = rsqrtf((float)(g_deg[i] + 1));  // +1 self loop
}

// -------- hierarchical scan --------
__global__ __launch_bounds__(SCB) void k_scan1(int n) {
    __shared__ int wsum[SCB / 32];
    int tid = threadIdx.x, lane = tid & 31, wid = tid >> 5;
    int i = blockIdx.x * SCB + tid;
    int v = (i < n) ? g_deg[i] : 0;
    int inc = v;
    #pragma unroll
    for (int o = 1; o < 32; o <<= 1) {
        int t = __shfl_up_sync(0xffffffffu, inc, o);
        if (lane >= o) inc += t;
    }
    if (lane == 31) wsum[wid] = inc;
    __syncthreads();
    if (wid == 0) {
        int w = (lane < SCB / 32) ? wsum[lane] : 0;
        #pragma unroll
        for (int o = 1; o < SCB / 32; o <<= 1) {
            int t = __shfl_up_sync(0xffffffffu, w, o);
            if (lane >= o) w += t;
        }
        if (lane < SCB / 32) wsum[lane] = w;
    }
    __syncthreads();
    int ex = (inc - v) + (wid ? wsum[wid - 1] : 0);
    if (i < n) g_off[i] = ex;
    if (tid == SCB - 1) g_bsum[blockIdx.x] = ex + v;
}

__global__ void k_scan2() {
    int lane = threadIdx.x;
    int carry = 0;
    for (int b = 0; b < NSB; b += 32) {
        int idx = b + lane;
        int v = (idx < NSB) ? g_bsum[idx] : 0;
        int inc = v;
        #pragma unroll
        for (int o = 1; o < 32; o <<= 1) {
            int t = __shfl_up_sync(0xffffffffu, inc, o);
            if (lane >= o) inc += t;
        }
        int ex = carry + inc - v;
        if (idx < NSB) g_bsum[idx] = ex;
        carry += __shfl_sync(0xffffffffu, inc, 31);
    }
}

__global__ void k_scan3(int n, int e_total) {
    int i = blockIdx.x * blockDim.x + threadIdx.x;
    if (i < n) {
        int o = g_off[i] + g_bsum[i / SCB];
        g_off[i] = o;
        g_cursor[i] = o;
    }
    if (i == 0) g_off[n] = e_total;
}

__global__ void k_scatter(const void* __restrict__ ei, int e) {
    int t = blockIdx.x * blockDim.x + threadIdx.x;
    if (t >= e) return;
    int s;
    if (g_is64) s = (int)((const long long*)ei)[t];
    else        s = ((const int*)ei)[t];
    int d = g_dst[t];
    int p = atomicAdd(&g_cursor[d], 1);
    g_csrw[p] = make_int2(s, __float_as_int(g_dinv[s]));
}

// ---------------- data conversion ----------------
__global__ void k_xhalf(const float* __restrict__ x, int total4) {
    int i = blockIdx.x * blockDim.x + threadIdx.x;
    if (i >= total4) return;
    float4 v = ((const float4*)x)[i];
    ((__half2*)g_xh)[i * 2] = __floats2half2_rn(v.x, v.y);
    ((__half2*)g_xh)[i * 2 + 1] = __floats2half2_rn(v.z, v.w);
}

__global__ void k_wsplit(const float* __restrict__ w10, const float* __restrict__ w11,
                         const float* __restrict__ w12, const float* __restrict__ w20,
                         const float* __restrict__ w21, const float* __restrict__ w22) {
    int g = blockIdx.x * blockDim.x + threadIdx.x;
    if (g < 384 * 256) {
        int n = g / 256, k = g % 256;
        const float* w = (n < 128) ? w10 : (n < 256) ? w11 : w12;
        g_w1t[g] = __float2half_rn(w[k * 128 + (n & 127)]);
    } else if (g < 384 * 256 + 120 * 384) {
        int g2 = g - 384 * 256;
        int n = g2 / 384, k = g2 % 384;
        const float* w = (n < 40) ? w20 : (n < 80) ? w21 : w22;
        g_w2t[g2] = __float2half_rn(w[k * 40 + (n % 40)]);
    }
}

// ---------------- mma.sync GEMM (fp16, sync loads — best measured variant) ----------------
#define SPITCH 72
#define OFF_A 0
#define OFF_B (128 * SPITCH)
#define SMEMSZ (2 * 128 * SPITCH * 2)  // 36864 bytes

__device__ __forceinline__ void ld_tile_sm(__half* dst, const __half* __restrict__ src,
                                           int row0, int validRows, int pitch, int k0, int tid) {
    #pragma unroll
    for (int it = 0; it < 4; it++) {
        int slot = tid + it * 256;
        int row = slot >> 3, q = slot & 7;
        float4 v = make_float4(0.f, 0.f, 0.f, 0.f);
        if (row < validRows)
            v = *reinterpret_cast<const float4*>(src + (size_t)(row0 + row) * pitch + k0 + q * 8);
        *reinterpret_cast<float4*>(dst + row * SPITCH + q * 8) = v;
    }
}

template <int LAYER>
__global__ __launch_bounds__(256) void k_mma(const float* __restrict__ b1, int M) {
    constexpr int K = (LAYER == 1) ? 256 : 384;
    constexpr int CH = K / 64;
    constexpr int APITCH = (LAYER == 1) ? 256 : 384;
    constexpr int BROWS = (LAYER == 1) ? 128 : 120;

    extern __shared__ __align__(16) __half sm[];
    uint32_t sbase = smem_u32(sm);

    int tid = threadIdx.x;
    int warp = tid >> 5, lane = tid & 31;
    int wm = warp & 3, wn = warp >> 2;
    int rowSel = lane & 15;
    int kSel = (lane >> 4) << 3;

    int bm = blockIdx.y * 128, bn = blockIdx.x * 128;
    int rowsA = M - bm; if (rowsA > 128) rowsA = 128;

    const __half* Ah = (LAYER == 1) ? g_xh : g_hh;
    const __half* Bh = (LAYER == 1) ? g_w1t : g_w2t;

    float acc[2][8][4];
    #pragma unroll
    for (int i = 0; i < 2; i++)
        #pragma unroll
        for (int j = 0; j < 8; j++)
            #pragma unroll
            for (int q = 0; q < 4; q++) acc[i][j][q] = 0.f;

    for (int c = 0; c < CH; c++) {
        int k0 = c * 64;
        ld_tile_sm(sm + OFF_A, Ah, bm, rowsA, APITCH, k0, tid);
        ld_tile_sm(sm + OFF_B, Bh, bn, BROWS, K, k0, tid);
        __syncthreads();
        #pragma unroll
        for (int kb = 0; kb < 64; kb += 16) {
            uint32_t aH[2][4];
            #pragma unroll
            for (int i = 0; i < 2; i++) {
                uint32_t rowA = wm * 32 + i * 16 + rowSel;
                ldm_x4(aH[i], sbase + 2u * (OFF_A + rowA * SPITCH + kb + kSel));
            }
            #pragma unroll
            for (int jj = 0; jj < 4; jj++) {
                uint32_t bH[4];
                uint32_t rowB = wn * 64 + jj * 16 + rowSel;
                ldm_x4(bH, sbase + 2u * (OFF_B + rowB * SPITCH + kb + kSel));
                #pragma unroll
                for (int i = 0; i < 2; i++) {
                    mma_f16(acc[i][2 * jj], aH[i], bH[0], bH[2]);
                    mma_f16(acc[i][2 * jj + 1], aH[i], bH[1], bH[3]);
                }
            }
        }
        __syncthreads();
    }

    int g = lane >> 2, tg = lane & 3;
    int m0 = bm + wm * 32;
    int nb = wn * 64;
    #pragma unroll
    for (int i = 0; i < 2; i++) {
        int r0 = m0 + i * 16 + g;
        int r1 = r0 + 8;
        #pragma unroll
        for (int j = 0; j < 8; j++) {
            int cl = nb + j * 8 + tg * 2;
            float2 v0 = make_float2(acc[i][j][0], acc[i][j][1]);
            float2 v1 = make_float2(acc[i][j][2], acc[i][j][3]);
            if (LAYER == 1) {
                if (blockIdx.x == 0) {
                    float2 bb = *(const float2*)&b1[cl];
                    if (r0 < M)
                        *(__half2*)&g_hh[(size_t)r0 * 384 + cl] = __floats2half2_rn(
                            fmaxf(v0.x + bb.x, 0.f), fmaxf(v0.y + bb.y, 0.f));
                    if (r1 < M)
                        *(__half2*)&g_hh[(size_t)r1 * 384 + cl] = __floats2half2_rn(
                            fmaxf(v1.x + bb.x, 0.f), fmaxf(v1.y + bb.y, 0.f));
                } else {
                    int cg = (blockIdx.x - 1) * 128 + cl;
                    if (r0 < M)
                        *(__half2*)&g_Gh[(size_t)r0 * 256 + cg] = __floats2half2_rn(v0.x, v0.y);
                    if (r1 < M)
                        *(__half2*)&g_Gh[(size_t)r1 * 256 + cg] = __floats2half2_rn(v1.x, v1.y);
                }
            } else {
                if (cl < 120) {
                    if (r0 < M) {
                        *(float2*)&g_Fb[(size_t)r0 * 120 + cl] = v0;
                        if (cl >= 40)
                            *(__half2*)&g_Fh[(size_t)r0 * 80 + (cl - 40)] = __floats2half2_rn(v0.x, v0.y);
                    }
                    if (r1 < M) {
                        *(float2*)&g_Fb[(size_t)r1 * 120 + cl] = v1;
                        if (cl >= 40)
                            *(__half2*)&g_Fh[(size_t)r1 * 80 + (cl - 40)] = __floats2half2_rn(v1.x, v1.y);
                    }
                }
            }
        }
    }
}

// ---------------- SpMM (fp16 gather, fp32 accumulate): one warp per row ----------------
// WHICH 0: g_Gh(256) -> h[:,128:256] (fp16 relu+b1) + g_Uh(128)
// WHICH 1: g_Uh(128) -> h[:,256:384] (fp16 relu+b1)
// WHICH 2: g_Fh(80)  -> g_Rb(80 fp32) + g_Rh(40)
// WHICH 3: g_Rh(40)  -> fused bias + log_softmax -> out
template <int NH, int WHICH>
__global__ __launch_bounds__(256) void k_spmmh(const float* __restrict__ b1,
                                               const float* __restrict__ b2,
                                               float* __restrict__ out, int n) {
    constexpr int IT = (NH + 127) / 128;
    const __half* __restrict__ in =
        (WHICH == 0) ? g_Gh : (WHICH == 1) ? g_Uh : (WHICH == 2) ? g_Fh : g_Rh;

    int w = (blockIdx.x * blockDim.x + threadIdx.x) >> 5;
    int lane = threadIdx.x & 31;
    if (w >= n) return;
    float di = g_dinv[w];

    float4 acc[IT];
    #pragma unroll
    for (int t = 0; t < IT; t++) {
        int c = t * 128 + lane * 4;
        acc[t] = make_float4(0, 0, 0, 0);
        if (c < NH) {
            uint2 u = *(const uint2*)(in + (size_t)w * NH + c);
            float2 f0 = __half22float2(*(__half2*)&u.x);
            float2 f1 = __half22float2(*(__half2*)&u.y);
            acc[t] = make_float4(di * f0.x, di * f0.y, di * f1.x, di * f1.y);
        }
    }
    int jb = g_off[w], je = g_off[w + 1];
    int2 nxt = make_int2(0, 0);
    if (jb < je) nxt = g_csrw[jb];
    for (int j = jb; j < je; j++) {
        int2 cur = nxt;
        if (j + 1 < je) nxt = g_csrw[j + 1];
        int s = cur.x;
        float ws = __int_as_float(cur.y);
        #pragma unroll
        for (int t = 0; t < IT; t++) {
            int c = t * 128 + lane * 4;
            if (c < NH) {
                uint2 u = __ldg((const uint2*)(in + (size_t)s * NH + c));
                float2 f0 = __half22float2(*(__half2*)&u.x);
                float2 f1 = __half22float2(*(__half2*)&u.y);
                acc[t].x += ws * f0.x;
                acc[t].y += ws * f0.y;
                acc[t].z += ws * f1.x;
                acc[t].w += ws * f1.y;
            }
        }
    }

    if (WHICH == 3) {
        // S row cols 0:40 live in lanes 0..9 (x4); fuse bias + log_softmax
        float4 sv = make_float4(di * acc[0].x, di * acc[0].y, di * acc[0].z, di * acc[0].w);
        float4 v = make_float4(0, 0, 0, 0);
        if (lane < 10)
            v = *(const float4*)&g_Fb[(size_t)w * 120 + lane * 4];
        else if (lane < 20)
            v = *(const float4*)&g_Rb[(size_t)w * 80 + (lane - 10) * 4];
        int srcl = (lane >= 20) ? (lane - 20) : 0;
        float sx = __shfl_sync(0xffffffffu, sv.x, srcl);
        float sy = __shfl_sync(0xffffffffu, sv.y, srcl);
        float sz = __shfl_sync(0xffffffffu, sv.z, srcl);
        float sw = __shfl_sync(0xffffffffu, sv.w, srcl);
        if (lane >= 20 && lane < 30) v = make_float4(sx, sy, sz, sw);
        bool act = lane < 30;
        if (act) {
            float4 bb = ((const float4*)b2)[lane];
            v.x += bb.x; v.y += bb.y; v.z += bb.z; v.w += bb.w;
        }
        float m = act ? fmaxf(fmaxf(v.x, v.y), fmaxf(v.z, v.w)) : -INFINITY;
        #pragma unroll
        for (int o = 16; o > 0; o >>= 1) m = fmaxf(m, __shfl_xor_sync(0xffffffffu, m, o));
        float s = 0.0f;
        if (act) s = expf(v.x - m) + expf(v.y - m) + expf(v.z - m) + expf(v.w - m);
        #pragma unroll
        for (int o = 16; o > 0; o >>= 1) s += __shfl_xor_sync(0xffffffffu, s, o);
        float lse = m + logf(s);
        if (act) {
            float4 r = make_float4(v.x - lse, v.y - lse, v.z - lse, v.w - lse);
            ((float4*)out)[(size_t)w * 30 + lane] = r;
        }
        return;
    }

    #pragma unroll
    for (int t = 0; t < IT; t++) {
        int c = t * 128 + lane * 4;
        if (c >= NH) continue;
        float4 ov = make_float4(di * acc[t].x, di * acc[t].y, di * acc[t].z, di * acc[t].w);
        if (WHICH == 0) {
            if (c < 128) {
                int col = 128 + c;
                float4 bb = *(const float4*)&b1[col];
                __half2 q0 = __floats2half2_rn(fmaxf(ov.x + bb.x, 0.f), fmaxf(ov.y + bb.y, 0.f));
                __half2 q1 = __floats2half2_rn(fmaxf(ov.z + bb.z, 0.f), fmaxf(ov.w + bb.w, 0.f));
                *(__half2*)&g_hh[(size_t)w * 384 + col] = q0;
                *(__half2*)&g_hh[(size_t)w * 384 + col + 2] = q1;
            } else {
                __half2 q0 = __floats2half2_rn(ov.x, ov.y);
                __half2 q1 = __floats2half2_rn(ov.z, ov.w);
                uint2 u;
                u.x = *(uint32_t*)&q0;
                u.y = *(uint32_t*)&q1;
                *(uint2*)&g_Uh[(size_t)w * 128 + (c - 128)] = u;
            }
        } else if (WHICH == 1) {
            int col = 256 + c;
            float4 bb = *(const float4*)&b1[col];
            __half2 q0 = __floats2half2_rn(fmaxf(ov.x + bb.x, 0.f), fmaxf(ov.y + bb.y, 0.f));
            __half2 q1 = __floats2half2_rn(fmaxf(ov.z + bb.z, 0.f), fmaxf(ov.w + bb.w, 0.f));
            *(__half2*)&g_hh[(size_t)w * 384 + col] = q0;
            *(__half2*)&g_hh[(size_t)w * 384 + col + 2] = q1;
        } else {  // WHICH == 2
            *(float4*)&g_Rb[(size_t)w * 80 + c] = ov;
            if (c >= 40) {
                __half2 q0 = __floats2half2_rn(ov.x, ov.y);
                __half2 q1 = __floats2half2_rn(ov.z, ov.w);
                uint2 u;
                u.x = *(uint32_t*)&q0;
                u.y = *(uint32_t*)&q1;
                *(uint2*)&g_Rh[(size_t)w * 40 + (c - 40)] = u;
            }
        }
    }
}

// ---------------- launch ----------------
extern "C" void kernel_launch(void* const* d_in, const int* in_sizes, int n_in,
                              void* d_out, int out_size) {
    const float* x = (const float*)d_in[0];
    const void* ei = d_in[1];
    const float* W1_0 = (const float*)d_in[2];
    const float* W1_1 = (const float*)d_in[3];
    const float* W1_2 = (const float*)d_in[4];
    const float* b1 = (const float*)d_in[5];
    const float* W2_0 = (const float*)d_in[6];
    const float* W2_1 = (const float*)d_in[7];
    const float* W2_2 = (const float*)d_in[8];
    const float* b2 = (const float*)d_in[9];
    float* out = (float*)d_out;

    int n = in_sizes[0] / FIN;  // 50000
    int e = in_sizes[1] / 2;    // 800000

    static cudaStream_t s2 = nullptr;
    static cudaEvent_t evFork = nullptr, evJoin = nullptr;
    if (s2 == nullptr) {
        cudaStreamCreateWithFlags(&s2, cudaStreamNonBlocking);
        cudaEventCreateWithFlags(&evFork, cudaEventDisableTiming);
        cudaEventCreateWithFlags(&evJoin, cudaEventDisableTiming);
        cudaFuncSetAttribute(k_mma<1>, cudaFuncAttributeMaxDynamicSharedMemorySize, SMEMSZ);
        cudaFuncSetAttribute(k_mma<2>, cudaFuncAttributeMaxDynamicSharedMemorySize, SMEMSZ);
    }

    // ---- fork: graph preprocessing runs on s2, parallel to conversion+mma1 ----
    cudaEventRecord(evFork, 0);
    cudaStreamWaitEvent(s2, evFork, 0);

    k_zerodetect<<<(n + 255) / 256, 256, 0, s2>>>((const int2*)ei, n, e);
    k_convdeg<<<(e + 255) / 256, 256, 0, s2>>>(ei, e);
    k_dinv<<<(n + 255) / 256, 256, 0, s2>>>(n);
    k_scan1<<<NSB, SCB, 0, s2>>>(n);
    k_scan2<<<1, 32, 0, s2>>>();
    k_scan3<<<(n + 255) / 256, 256, 0, s2>>>(n, e);
    k_scatter<<<(e + 255) / 256, 256, 0, s2>>>(ei, e);
    cudaEventRecord(evJoin, s2);

    // ---- main branch: operand conversion + layer-1 GEMM ----
    k_xhalf<<<(n * FIN / 4 + 255) / 256, 256>>>(x, n * FIN / 4);
    k_wsplit<<<(384 * 256 + 120 * 384 + 255) / 256, 256>>>(W1_0, W1_1, W1_2, W2_0, W2_1, W2_2);

    int mt = (n + 127) / 128;
    int sb = (n + 7) / 8;

    k_mma<1><<<dim3(3, mt), 256, SMEMSZ>>>(b1, n);  // [h0 | Gh] = x @ [W0|W1|W2]

    // ---- join: SpMM chain needs the CSR ----
    cudaStreamWaitEvent(0, evJoin, 0);

    k_spmmh<256, 0><<<sb, 256>>>(b1, b2, out, n);  // U = P(G): h[:,128:256] + Uh
    k_spmmh<128, 1><<<sb, 256>>>(b1, b2, out, n);  // V = P(Uh): h[:,256:384]

    k_mma<2><<<dim3(1, mt), 256, SMEMSZ>>>(b1, n); // F = h @ [W0|W1|W2]
    k_spmmh<80, 2><<<sb, 256>>>(b1, b2, out, n);   // R = P(Fh)
    k_spmmh<40, 3><<<sb, 256>>>(b1, b2, out, n);   // S = P(Rh) + fused log_softmax
}